// round 6
// baseline (speedup 1.0000x reference)
#include <cuda_runtime.h>
#include <cuda_bf16.h>
#include <cstdint>

// Problem constants
#define VOCAB 50000
#define EMB   300
#define FILT  400
#define ATT   200
#define KW    3
#define BATCH 4096
#define SEQ   30
#define M2    (BATCH * SEQ)      // 122880 rows of (b,n)
#define GN    1280               // 3*400 = 1200 padded to 1280
#define NPAD  256                // ATT padded 200 -> 256

// ---------------------------------------------------------------------------
// Scratch (static device globals; allocation at module load, per harness rules)
// ---------------------------------------------------------------------------
__device__ float g_G[EMB * GN];              // rearranged conv weights [300 x 1280]
__device__ float g_P[VOCAB * GN];            // vocab projection       [50000 x 1280]
__device__ float g_C[M2 * FILT];             // relu(conv) activations [122880 x 400]
__device__ float g_VP[FILT * NPAD];          // padded v               [400 x 256]
__device__ float g_vbp[NPAD];                // padded vb
__device__ float g_qp[NPAD];                 // padded q
__device__ float g_scorep[2 * M2];           // partial scores (per N-column-block)
__device__ float g_alpha[M2];                // softmax*mask weights

// ---------------------------------------------------------------------------
// Kernel 0: rearrange weights.
//   G[e][j] with j = k*400 + f  = conv_w[f][e][k];  cols 1200..1279 zero.
//   VP[f][a] = v[f][a] for a<200 else 0;  vbp/qp similarly padded with zeros.
// ---------------------------------------------------------------------------
__global__ void prep_kernel(const float* __restrict__ conv_w,
                            const float* __restrict__ v,
                            const float* __restrict__ vb,
                            const float* __restrict__ q)
{
    int i      = blockIdx.x * blockDim.x + threadIdx.x;
    int stride = gridDim.x * blockDim.x;

    for (int idx = i; idx < EMB * GN; idx += stride) {
        int e = idx / GN, j = idx % GN;
        float val = 0.f;
        if (j < KW * FILT) {
            int k = j / FILT, f = j % FILT;
            val = conv_w[f * (EMB * KW) + e * KW + k];
        }
        g_G[idx] = val;
    }
    for (int idx = i; idx < FILT * NPAD; idx += stride) {
        int f = idx >> 8, a = idx & (NPAD - 1);
        g_VP[idx] = (a < ATT) ? v[f * ATT + a] : 0.f;
    }
    if (i < NPAD) {
        g_vbp[i] = (i < ATT) ? vb[i] : 0.f;
        g_qp[i]  = (i < ATT) ? q[i]  : 0.f;
    }
}

// ---------------------------------------------------------------------------
// SGEMM tile config: 128x128x8 block tile, 256 threads, 8x8 per thread.
// ---------------------------------------------------------------------------
#define BM 128
#define BN 128
#define BK 8
#define TM 8
#define TN 8

// GEMM 1:  g_P[50000 x 1280] = emb[50000 x 300] @ g_G[300 x 1280]
__global__ __launch_bounds__(256) void gemm_P_kernel(const float* __restrict__ A)
{
    const int M = VOCAB, K = EMB;
    __shared__ float As[BK][BM];
    __shared__ float Bs[BK][BN];

    int tid = threadIdx.x;
    int tx  = tid & 15, ty = tid >> 4;
    int bM  = blockIdx.y * BM;
    int bN  = blockIdx.x * BN;

    int arow = tid >> 1;          // 0..127
    int acol = (tid & 1) << 2;    // 0 or 4
    int brow = tid >> 5;          // 0..7
    int bcol = (tid & 31) << 2;   // 0..124

    float acc[TM][TN];
#pragma unroll
    for (int i = 0; i < TM; i++)
#pragma unroll
        for (int j = 0; j < TN; j++) acc[i][j] = 0.f;

    int gar = bM + arow;
    const float* Aptr = A + (size_t)gar * K;

    for (int k0 = 0; k0 < K; k0 += BK) {
        float a0 = 0.f, a1 = 0.f, a2 = 0.f, a3 = 0.f;
        int kc = k0 + acol;
        if (gar < M) {
            if (kc + 4 <= K) {
                float4 t = *(const float4*)(Aptr + kc);
                a0 = t.x; a1 = t.y; a2 = t.z; a3 = t.w;
            } else {
                if (kc + 0 < K) a0 = Aptr[kc + 0];
                if (kc + 1 < K) a1 = Aptr[kc + 1];
                if (kc + 2 < K) a2 = Aptr[kc + 2];
                if (kc + 3 < K) a3 = Aptr[kc + 3];
            }
        }
        As[acol + 0][arow] = a0; As[acol + 1][arow] = a1;
        As[acol + 2][arow] = a2; As[acol + 3][arow] = a3;

        float4 bv = make_float4(0.f, 0.f, 0.f, 0.f);
        int kr = k0 + brow;
        if (kr < K)
            bv = *(const float4*)(g_G + (size_t)kr * GN + bN + bcol);
        *(float4*)&Bs[brow][bcol] = bv;
        __syncthreads();

#pragma unroll
        for (int k = 0; k < BK; k++) {
            float ar[TM], br[TN];
            *(float4*)&ar[0] = *(const float4*)&As[k][ty * TM];
            *(float4*)&ar[4] = *(const float4*)&As[k][ty * TM + 4];
            *(float4*)&br[0] = *(const float4*)&Bs[k][tx * TN];
            *(float4*)&br[4] = *(const float4*)&Bs[k][tx * TN + 4];
#pragma unroll
            for (int i = 0; i < TM; i++)
#pragma unroll
                for (int j = 0; j < TN; j++)
                    acc[i][j] = fmaf(ar[i], br[j], acc[i][j]);
        }
        __syncthreads();
    }

#pragma unroll
    for (int i = 0; i < TM; i++) {
        int gr = bM + ty * TM + i;
        if (gr < M) {
            float* crow = g_P + (size_t)gr * GN + bN + tx * TN;
            *(float4*)(crow)     = *(float4*)&acc[i][0];
            *(float4*)(crow + 4) = *(float4*)&acc[i][4];
        }
    }
}

// ---------------------------------------------------------------------------
// Kernel 2: assemble conv output per (b,n) row via 3 gathered P rows.
//   C[m][f] = relu( P[t_{n-1}][k=0][f] + P[t_n][k=1][f] + P[t_{n+1}][k=2][f] + conv_b[f] )
// ---------------------------------------------------------------------------
__global__ void assemble_kernel(const int* __restrict__ title,
                                const float* __restrict__ conv_b)
{
    int m   = blockIdx.x;
    int tid = threadIdx.x;        // 128 threads, 100 active (100 float4 = 400)
    if (tid >= FILT / 4) return;
    int n = m % SEQ;
    int off = tid * 4;

    float4 acc = *(const float4*)(conv_b + off);

    int tcur = title[m];
    float4 x = *(const float4*)(g_P + (size_t)tcur * GN + 1 * FILT + off);
    acc.x += x.x; acc.y += x.y; acc.z += x.z; acc.w += x.w;

    if (n > 0) {
        int tp = title[m - 1];
        float4 y = *(const float4*)(g_P + (size_t)tp * GN + 0 * FILT + off);
        acc.x += y.x; acc.y += y.y; acc.z += y.z; acc.w += y.w;
    }
    if (n < SEQ - 1) {
        int tn = title[m + 1];
        float4 z = *(const float4*)(g_P + (size_t)tn * GN + 2 * FILT + off);
        acc.x += z.x; acc.y += z.y; acc.z += z.z; acc.w += z.w;
    }
    acc.x = fmaxf(acc.x, 0.f); acc.y = fmaxf(acc.y, 0.f);
    acc.z = fmaxf(acc.z, 0.f); acc.w = fmaxf(acc.w, 0.f);
    *(float4*)(g_C + (size_t)m * FILT + off) = acc;
}

// ---------------------------------------------------------------------------
// GEMM 3 + fused attention epilogue:
//   S = g_C[122880 x 400] @ g_VP[400 x 256]
//   scorep[col_block][m] = sum_a tanh(S[m,a] + vbp[a]) * qp[a]   (per column block)
// S never hits global memory. Padded cols: v=0 -> S=0, vb=0, q=0 -> contribute 0.
// ---------------------------------------------------------------------------
__global__ __launch_bounds__(256) void gemm_att_kernel()
{
    const int K = FILT;           // 400, multiple of 8
    __shared__ float As[BK][BM];
    __shared__ float Bs[BK][BN];
    __shared__ float red[BM][17]; // +1 pad to dodge bank conflicts

    int tid = threadIdx.x;
    int tx  = tid & 15, ty = tid >> 4;
    int bM  = blockIdx.y * BM;    // 960 blocks, exact fit
    int bN  = blockIdx.x * BN;    // 0 or 128

    int arow = tid >> 1;
    int acol = (tid & 1) << 2;
    int brow = tid >> 5;
    int bcol = (tid & 31) << 2;

    float acc[TM][TN];
#pragma unroll
    for (int i = 0; i < TM; i++)
#pragma unroll
        for (int j = 0; j < TN; j++) acc[i][j] = 0.f;

    const float* Aptr = g_C + (size_t)(bM + arow) * K;

    for (int k0 = 0; k0 < K; k0 += BK) {
        float4 av = *(const float4*)(Aptr + k0 + acol);
        As[acol + 0][arow] = av.x; As[acol + 1][arow] = av.y;
        As[acol + 2][arow] = av.z; As[acol + 3][arow] = av.w;
        float4 bv = *(const float4*)(g_VP + (size_t)(k0 + brow) * NPAD + bN + bcol);
        *(float4*)&Bs[brow][bcol] = bv;
        __syncthreads();

#pragma unroll
        for (int k = 0; k < BK; k++) {
            float ar[TM], br[TN];
            *(float4*)&ar[0] = *(const float4*)&As[k][ty * TM];
            *(float4*)&ar[4] = *(const float4*)&As[k][ty * TM + 4];
            *(float4*)&br[0] = *(const float4*)&Bs[k][tx * TN];
            *(float4*)&br[4] = *(const float4*)&Bs[k][tx * TN + 4];
#pragma unroll
            for (int i = 0; i < TM; i++)
#pragma unroll
                for (int j = 0; j < TN; j++)
                    acc[i][j] = fmaf(ar[i], br[j], acc[i][j]);
        }
        __syncthreads();
    }

    // Fused epilogue: tanh(S + vb) * q, reduced over this block's 128 columns.
    float rowpart[TM];
#pragma unroll
    for (int i = 0; i < TM; i++) rowpart[i] = 0.f;
#pragma unroll
    for (int j = 0; j < TN; j++) {
        int gc = bN + tx * TN + j;
        float vbv = g_vbp[gc];
        float qv  = g_qp[gc];
#pragma unroll
        for (int i = 0; i < TM; i++)
            rowpart[i] += tanhf(acc[i][j] + vbv) * qv;
    }
    __syncthreads();
#pragma unroll
    for (int i = 0; i < TM; i++)
        red[ty * TM + i][tx] = rowpart[i];
    __syncthreads();
    if (tid < BM) {
        float s = 0.f;
#pragma unroll
        for (int t = 0; t < 16; t++) s += red[tid][t];
        g_scorep[(size_t)blockIdx.x * M2 + bM + tid] = s;   // disjoint: deterministic
    }
}

// ---------------------------------------------------------------------------
// Kernel 4: softmax over the BATCH dimension (per sequence position n),
// then multiply by the nonzero-token mask.
// ---------------------------------------------------------------------------
__global__ void softmax_kernel(const int* __restrict__ title)
{
    int n   = blockIdx.x;         // 0..29
    int tid = threadIdx.x;        // 256
    __shared__ float red[256];

    float mx = -3.4e38f;
    for (int b = tid; b < BATCH; b += 256) {
        int m = b * SEQ + n;
        float s = g_scorep[m] + g_scorep[M2 + m];
        mx = fmaxf(mx, s);
    }
    red[tid] = mx;
    __syncthreads();
    for (int off = 128; off > 0; off >>= 1) {
        if (tid < off) red[tid] = fmaxf(red[tid], red[tid + off]);
        __syncthreads();
    }
    mx = red[0];
    __syncthreads();

    float sum = 0.f;
    for (int b = tid; b < BATCH; b += 256) {
        int m = b * SEQ + n;
        float s = g_scorep[m] + g_scorep[M2 + m];
        sum += expf(s - mx);
    }
    red[tid] = sum;
    __syncthreads();
    for (int off = 128; off > 0; off >>= 1) {
        if (tid < off) red[tid] += red[tid + off];
        __syncthreads();
    }
    float inv = 1.f / red[0];

    for (int b = tid; b < BATCH; b += 256) {
        int m = b * SEQ + n;
        float s  = g_scorep[m] + g_scorep[M2 + m];
        float al = expf(s - mx) * inv;
        if (title[m] == 0) al = 0.f;
        g_alpha[m] = al;
    }
}

// ---------------------------------------------------------------------------
// Kernel 5: pooling  out[b][f] = sum_n alpha[b,n] * C[b,n,f]
// ---------------------------------------------------------------------------
__global__ void pool_kernel(float* __restrict__ out)
{
    int b   = blockIdx.x;         // 0..4095
    int tid = threadIdx.x;        // 128
    __shared__ float al[SEQ];
    if (tid < SEQ) al[tid] = g_alpha[b * SEQ + tid];
    __syncthreads();
    if (tid >= FILT / 4) return;
    int off = tid * 4;
    const float* base = g_C + (size_t)b * SEQ * FILT + off;
    float4 acc = make_float4(0.f, 0.f, 0.f, 0.f);
#pragma unroll
    for (int n = 0; n < SEQ; n++) {
        float a = al[n];
        float4 c = *(const float4*)(base + (size_t)n * FILT);
        acc.x = fmaf(a, c.x, acc.x); acc.y = fmaf(a, c.y, acc.y);
        acc.z = fmaf(a, c.z, acc.z); acc.w = fmaf(a, c.w, acc.w);
    }
    *(float4*)(out + (size_t)b * FILT + off) = acc;
}

// ---------------------------------------------------------------------------
// Launch: graph-capturable, allocation-free, deterministic.
// Input order per metadata: encoded_title, emb, conv_w, conv_b, v, vb, q
// ---------------------------------------------------------------------------
extern "C" void kernel_launch(void* const* d_in, const int* in_sizes, int n_in,
                              void* d_out, int out_size)
{
    const int*   title  = (const int*)  d_in[0];
    const float* emb    = (const float*)d_in[1];
    const float* conv_w = (const float*)d_in[2];
    const float* conv_b = (const float*)d_in[3];
    const float* v      = (const float*)d_in[4];
    const float* vb     = (const float*)d_in[5];
    const float* q      = (const float*)d_in[6];
    float*       out    = (float*)d_out;

    prep_kernel<<<512, 256>>>(conv_w, v, vb, q);

    dim3 g1(GN / BN, (VOCAB + BM - 1) / BM);         // (10, 391)
    gemm_P_kernel<<<g1, 256>>>(emb);

    assemble_kernel<<<M2, 128>>>(title, conv_b);

    dim3 g3(NPAD / BN, M2 / BM);                     // (2, 960)
    gemm_att_kernel<<<g3, 256>>>();

    softmax_kernel<<<SEQ, 256>>>(title);

    pool_kernel<<<BATCH, 128>>>(out);
}

// round 11
// speedup vs baseline: 1.9908x; 1.9908x over previous
#include <cuda_runtime.h>
#include <cuda_bf16.h>
#include <cstdint>

// Problem constants
#define VOCAB 50000
#define MPAD  50048              // 391 * 128
#define EMB   300
#define FILT  400
#define ATT   200
#define KW    3
#define BATCH 4096
#define SEQ   30
#define M2    (BATCH * SEQ)      // 122880
#define GN    1280               // 3*400 padded to 1280
#define NPAD  256                // ATT padded 200 -> 256

// GEMM1 split-K:  3 terms * 320 (EMB padded 300->320)
#define KC1   960
#define NC1   15                 // 960/64
// GEMM2 split-K:  3 terms * 400 = 1200, padded to 1216 (64-multiple)
#define KC2   1216
#define NC2   19                 // 1216/64

// ---------------------------------------------------------------------------
// Scratch (static device globals; zero-initialized at module load)
// ---------------------------------------------------------------------------
__device__ __nv_bfloat16 g_Abf[(size_t)MPAD * KC1];  // emb split [hi|lo|hi]
__device__ __nv_bfloat16 g_Bbf[(size_t)GN * KC1];    // G split  [hi;hi;lo], [N][K]
__device__ float         g_P[(size_t)VOCAB * GN];    // vocab projection fp32
__device__ float         g_C[(size_t)M2 * FILT];     // relu(conv) fp32 (for pooling)
__device__ __nv_bfloat16 g_Cbf[(size_t)M2 * KC2];    // relu(conv) split [hi|lo|hi|0]
__device__ __nv_bfloat16 g_VPbf[(size_t)NPAD * KC2]; // v split [hi|hi|lo|0], [N][K]
__device__ float         g_vbp[NPAD];
__device__ float         g_qp[NPAD];
__device__ float         g_scorep[2 * M2];
__device__ float         g_alpha[M2];

// ---------------------------------------------------------------------------
// Kernel 0: build bf16-split operands + padded attention weights.
// ---------------------------------------------------------------------------
__global__ void prep_kernel(const float* __restrict__ emb,
                            const float* __restrict__ conv_w,
                            const float* __restrict__ v,
                            const float* __restrict__ vb,
                            const float* __restrict__ q)
{
    size_t i      = (size_t)blockIdx.x * blockDim.x + threadIdx.x;
    size_t stride = (size_t)gridDim.x * blockDim.x;

    // A' = emb split: term t=k'/320 in {hi, lo, hi}; k' pad 300..319 zero
    for (size_t idx = i; idx < (size_t)VOCAB * KC1; idx += stride) {
        int m  = (int)(idx / KC1);
        int kp = (int)(idx % KC1);
        int t  = kp / 320, k = kp - t * 320;
        float out = 0.f;
        if (k < EMB) {
            float x  = emb[(size_t)m * EMB + k];
            float hi = __bfloat162float(__float2bfloat16(x));
            out = (t == 1) ? (x - hi) : hi;
        }
        g_Abf[idx] = __float2bfloat16(out);
    }

    // B' = G split, N-major: n = kk*400+f, G[k][n] = conv_w[f][k][kk]
    // terms {hi, hi, lo}
    for (size_t idx = i; idx < (size_t)GN * KC1; idx += stride) {
        int n  = (int)(idx / KC1);
        int kp = (int)(idx % KC1);
        int t  = kp / 320, k = kp - t * 320;
        float out = 0.f;
        if (k < EMB && n < KW * FILT) {
            int kk = n / FILT, f = n - kk * FILT;
            float x  = conv_w[(size_t)f * (EMB * KW) + k * KW + kk];
            float hi = __bfloat162float(__float2bfloat16(x));
            out = (t == 2) ? (x - hi) : hi;
        }
        g_Bbf[idx] = __float2bfloat16(out);
    }

    // VP' = v split, N-major over attention cols: VP'[a][t*400+f] from v[f][a],
    // terms {hi, hi, lo}; rows a>=200 and cols >=1200 zero.
    for (size_t idx = i; idx < (size_t)NPAD * KC2; idx += stride) {
        int a  = (int)(idx / KC2);
        int kp = (int)(idx % KC2);
        float out = 0.f;
        if (kp < 1200 && a < ATT) {
            int t = kp / 400, f = kp - t * 400;
            float x  = v[(size_t)f * ATT + a];
            float hi = __bfloat162float(__float2bfloat16(x));
            out = (t == 2) ? (x - hi) : hi;
        }
        g_VPbf[idx] = __float2bfloat16(out);
    }

    if (i < NPAD) {
        g_vbp[i] = (i < ATT) ? vb[i] : 0.f;
        g_qp[i]  = (i < ATT) ? q[i]  : 0.f;
    }
}

// ---------------------------------------------------------------------------
// HMMA helpers (sm_80-era instructions: compile on family target)
// ---------------------------------------------------------------------------
__device__ __forceinline__ uint32_t smem_u32(const void* p) {
    uint32_t r;
    asm("{ .reg .u64 t; cvta.to.shared.u64 t, %1; cvt.u32.u64 %0, t; }"
        : "=r"(r) : "l"(p));
    return r;
}
#define SWZ(x) ((x) ^ (((x) >> 3) & 0x70))

__device__ __forceinline__ void ldm4(uint32_t* r, uint32_t addr) {
    asm volatile("ldmatrix.sync.aligned.m8n8.x4.shared.b16 {%0,%1,%2,%3}, [%4];"
                 : "=r"(r[0]), "=r"(r[1]), "=r"(r[2]), "=r"(r[3]) : "r"(addr));
}
__device__ __forceinline__ void mma16816(float* c, const uint32_t* a,
                                         uint32_t b0, uint32_t b1) {
    asm volatile(
        "mma.sync.aligned.m16n8k16.row.col.f32.bf16.bf16.f32 "
        "{%0,%1,%2,%3}, {%4,%5,%6,%7}, {%8,%9}, {%0,%1,%2,%3};"
        : "+f"(c[0]), "+f"(c[1]), "+f"(c[2]), "+f"(c[3])
        : "r"(a[0]), "r"(a[1]), "r"(a[2]), "r"(a[3]), "r"(b0), "r"(b1));
}
__device__ __forceinline__ void cpasync16(uint32_t s, const void* g) {
    asm volatile(
        "{ .reg .u64 ga; cvta.to.global.u64 ga, %1; "
        "cp.async.cg.shared.global [%0], [ga], 16; }"
        :: "r"(s), "l"(g) : "memory");
}
#define CP_COMMIT() asm volatile("cp.async.commit_group;" ::: "memory")
#define CP_WAIT1()  asm volatile("cp.async.wait_group 1;" ::: "memory")
#define CP_WAIT0()  asm volatile("cp.async.wait_group 0;" ::: "memory")

#define DYN_SMEM 65536           // 2 stages x (16KB A + 16KB B)

// ---------------------------------------------------------------------------
// GEMM 1 (HMMA): g_P[50048 x 1280] = A'[.,960] @ B'^T, fp32 accum.
// Block 128x128, warps 2(m)x4(n), warp tile 64x32, BK=64, cp.async 2-stage.
// ---------------------------------------------------------------------------
__global__ __launch_bounds__(256) void gemm_P_mma()
{
    extern __shared__ __align__(128) uint8_t dyn[];
    int tid = threadIdx.x, w = tid >> 5, lane = tid & 31;
    int bM = blockIdx.y * 128, bN = blockIdx.x * 128;
    int wm = (w & 1) * 64, wn = (w >> 1) * 32;
    uint32_t sbase = smem_u32(dyn);

    float acc[4][4][4];
#pragma unroll
    for (int i = 0; i < 4; i++)
#pragma unroll
        for (int j = 0; j < 4; j++)
#pragma unroll
            for (int k = 0; k < 4; k++) acc[i][j][k] = 0.f;

    auto issue = [&](int c, int b) {
        uint32_t sA = sbase + b * 32768, sB = sA + 16384;
        size_t k0 = (size_t)c * 64;
#pragma unroll
        for (int i = 0; i < 4; i++) {
            int ch = i * 256 + tid, row = ch >> 3, c16 = ch & 7;
            uint32_t so = SWZ((uint32_t)(row * 128 + c16 * 16));
            cpasync16(sA + so, g_Abf + (size_t)(bM + row) * KC1 + k0 + c16 * 8);
            cpasync16(sB + so, g_Bbf + (size_t)(bN + row) * KC1 + k0 + c16 * 8);
        }
        CP_COMMIT();
    };

    issue(0, 0);
    for (int c = 0; c < NC1; c++) {
        int b = c & 1;
        if (c + 1 < NC1) { issue(c + 1, b ^ 1); CP_WAIT1(); }
        else             { CP_WAIT0(); }
        __syncthreads();
        uint32_t sA = sbase + b * 32768, sB = sA + 16384;
#pragma unroll
        for (int ks = 0; ks < 4; ks++) {
            uint32_t af[4][4], bf2[2][4];
#pragma unroll
            for (int mi = 0; mi < 4; mi++)
                ldm4(af[mi], sA + SWZ((uint32_t)((wm + mi * 16 + (lane & 15)) * 128
                                                 + ks * 32 + (lane >> 4) * 16)));
#pragma unroll
            for (int bj = 0; bj < 2; bj++)
                ldm4(bf2[bj], sB + SWZ((uint32_t)((wn + bj * 16 + (lane & 15)) * 128
                                                  + ks * 32 + (lane >> 4) * 16)));
#pragma unroll
            for (int mi = 0; mi < 4; mi++)
#pragma unroll
                for (int nb = 0; nb < 4; nb++)
                    mma16816(acc[mi][nb], af[mi],
                             bf2[nb >> 1][nb & 1], bf2[nb >> 1][(nb & 1) + 2]);
        }
        __syncthreads();
    }

    int r0 = lane >> 2, cB = (lane & 3) * 2;
#pragma unroll
    for (int mi = 0; mi < 4; mi++) {
        int row = bM + wm + mi * 16 + r0;
#pragma unroll
        for (int nb = 0; nb < 4; nb++) {
            int col = bN + wn + nb * 8 + cB;
            if (row < VOCAB)
                *(float2*)(g_P + (size_t)row * GN + col)
                    = make_float2(acc[mi][nb][0], acc[mi][nb][1]);
            if (row + 8 < VOCAB)
                *(float2*)(g_P + (size_t)(row + 8) * GN + col)
                    = make_float2(acc[mi][nb][2], acc[mi][nb][3]);
        }
    }
}

// ---------------------------------------------------------------------------
// Kernel 2: assemble conv rows (3 gathered P rows + bias, relu), write fp32 C
// for pooling AND the bf16 split [hi|lo|hi] rows for the attention GEMM.
// ---------------------------------------------------------------------------
__global__ void assemble_kernel(const int* __restrict__ title,
                                const float* __restrict__ conv_b)
{
    int m   = blockIdx.x;
    int tid = threadIdx.x;
    if (tid >= FILT / 4) return;
    int n = m % SEQ;
    int off = tid * 4;

    float4 acc = *(const float4*)(conv_b + off);

    int tcur = title[m];
    float4 x = *(const float4*)(g_P + (size_t)tcur * GN + 1 * FILT + off);
    acc.x += x.x; acc.y += x.y; acc.z += x.z; acc.w += x.w;

    if (n > 0) {
        int tp = title[m - 1];
        float4 y = *(const float4*)(g_P + (size_t)tp * GN + 0 * FILT + off);
        acc.x += y.x; acc.y += y.y; acc.z += y.z; acc.w += y.w;
    }
    if (n < SEQ - 1) {
        int tn = title[m + 1];
        float4 z = *(const float4*)(g_P + (size_t)tn * GN + 2 * FILT + off);
        acc.x += z.x; acc.y += z.y; acc.z += z.z; acc.w += z.w;
    }
    acc.x = fmaxf(acc.x, 0.f); acc.y = fmaxf(acc.y, 0.f);
    acc.z = fmaxf(acc.z, 0.f); acc.w = fmaxf(acc.w, 0.f);
    *(float4*)(g_C + (size_t)m * FILT + off) = acc;

    // bf16 split
    float vv[4] = {acc.x, acc.y, acc.z, acc.w};
    unsigned short hu[4], lu[4];
#pragma unroll
    for (int i = 0; i < 4; i++) {
        __nv_bfloat16 h = __float2bfloat16(vv[i]);
        float lo = vv[i] - __bfloat162float(h);
        hu[i] = __bfloat16_as_ushort(h);
        lu[i] = __bfloat16_as_ushort(__float2bfloat16(lo));
    }
    uint2 hv = make_uint2((uint32_t)hu[0] | ((uint32_t)hu[1] << 16),
                          (uint32_t)hu[2] | ((uint32_t)hu[3] << 16));
    uint2 lv = make_uint2((uint32_t)lu[0] | ((uint32_t)lu[1] << 16),
                          (uint32_t)lu[2] | ((uint32_t)lu[3] << 16));
    __nv_bfloat16* cb = g_Cbf + (size_t)m * KC2;
    *(uint2*)(cb + off)       = hv;
    *(uint2*)(cb + 400 + off) = lv;
    *(uint2*)(cb + 800 + off) = hv;
    // cols 1200..1215 stay zero (zero-initialized global, never written)
}

// ---------------------------------------------------------------------------
// GEMM 3 (HMMA) + fused attention epilogue:
//   S = Cbf[122880 x 1216] @ VPbf^T[256 x 1216]
//   scorep[col_block][m] = sum_a tanh(S[m,a]+vb[a]) * q[a]
// ---------------------------------------------------------------------------
__global__ __launch_bounds__(256) void gemm_att_mma()
{
    extern __shared__ __align__(128) uint8_t dyn[];
    int tid = threadIdx.x, w = tid >> 5, lane = tid & 31;
    int bM = blockIdx.y * 128, bN = blockIdx.x * 128;
    int wm = (w & 1) * 64, wn = (w >> 1) * 32;
    uint32_t sbase = smem_u32(dyn);

    float acc[4][4][4];
#pragma unroll
    for (int i = 0; i < 4; i++)
#pragma unroll
        for (int j = 0; j < 4; j++)
#pragma unroll
            for (int k = 0; k < 4; k++) acc[i][j][k] = 0.f;

    auto issue = [&](int c, int b) {
        uint32_t sA = sbase + b * 32768, sB = sA + 16384;
        size_t k0 = (size_t)c * 64;
#pragma unroll
        for (int i = 0; i < 4; i++) {
            int ch = i * 256 + tid, row = ch >> 3, c16 = ch & 7;
            uint32_t so = SWZ((uint32_t)(row * 128 + c16 * 16));
            cpasync16(sA + so, g_Cbf  + (size_t)(bM + row) * KC2 + k0 + c16 * 8);
            cpasync16(sB + so, g_VPbf + (size_t)(bN + row) * KC2 + k0 + c16 * 8);
        }
        CP_COMMIT();
    };

    issue(0, 0);
    for (int c = 0; c < NC2; c++) {
        int b = c & 1;
        if (c + 1 < NC2) { issue(c + 1, b ^ 1); CP_WAIT1(); }
        else             { CP_WAIT0(); }
        __syncthreads();
        uint32_t sA = sbase + b * 32768, sB = sA + 16384;
#pragma unroll
        for (int ks = 0; ks < 4; ks++) {
            uint32_t af[4][4], bf2[2][4];
#pragma unroll
            for (int mi = 0; mi < 4; mi++)
                ldm4(af[mi], sA + SWZ((uint32_t)((wm + mi * 16 + (lane & 15)) * 128
                                                 + ks * 32 + (lane >> 4) * 16)));
#pragma unroll
            for (int bj = 0; bj < 2; bj++)
                ldm4(bf2[bj], sB + SWZ((uint32_t)((wn + bj * 16 + (lane & 15)) * 128
                                                  + ks * 32 + (lane >> 4) * 16)));
#pragma unroll
            for (int mi = 0; mi < 4; mi++)
#pragma unroll
                for (int nb = 0; nb < 4; nb++)
                    mma16816(acc[mi][nb], af[mi],
                             bf2[nb >> 1][nb & 1], bf2[nb >> 1][(nb & 1) + 2]);
        }
        __syncthreads();
    }

    // Fused epilogue: per-row sum of tanh(S+vb)*q over this block's 128 cols.
    float rp[4][2];
#pragma unroll
    for (int mi = 0; mi < 4; mi++) { rp[mi][0] = 0.f; rp[mi][1] = 0.f; }
#pragma unroll
    for (int nb = 0; nb < 4; nb++) {
        int gc = bN + wn + nb * 8 + (lane & 3) * 2;
        float vb0 = g_vbp[gc], vb1 = g_vbp[gc + 1];
        float q0  = g_qp[gc],  q1  = g_qp[gc + 1];
#pragma unroll
        for (int mi = 0; mi < 4; mi++) {
            rp[mi][0] += tanhf(acc[mi][nb][0] + vb0) * q0
                       + tanhf(acc[mi][nb][1] + vb1) * q1;
            rp[mi][1] += tanhf(acc[mi][nb][2] + vb0) * q0
                       + tanhf(acc[mi][nb][3] + vb1) * q1;
        }
    }
#pragma unroll
    for (int mi = 0; mi < 4; mi++)
#pragma unroll
        for (int h = 0; h < 2; h++) {
            rp[mi][h] += __shfl_xor_sync(0xffffffffu, rp[mi][h], 1);
            rp[mi][h] += __shfl_xor_sync(0xffffffffu, rp[mi][h], 2);
        }

    float* red = (float*)dyn;     // reuse tile SMEM (all reads done)
    if ((lane & 3) == 0) {
#pragma unroll
        for (int mi = 0; mi < 4; mi++)
#pragma unroll
            for (int h = 0; h < 2; h++) {
                int row = wm + mi * 16 + (lane >> 2) + h * 8;
                red[row * 4 + (w >> 1)] = rp[mi][h];
            }
    }
    __syncthreads();
    if (tid < 128) {
        float s = red[tid * 4 + 0] + red[tid * 4 + 1]
                + red[tid * 4 + 2] + red[tid * 4 + 3];
        g_scorep[(size_t)blockIdx.x * M2 + bM + tid] = s;
    }
}

// ---------------------------------------------------------------------------
// Kernel 4: softmax over batch dim (per position n), masked.
// ---------------------------------------------------------------------------
__global__ void softmax_kernel(const int* __restrict__ title)
{
    int n   = blockIdx.x;
    int tid = threadIdx.x;
    __shared__ float red[256];

    float mx = -3.4e38f;
    for (int b = tid; b < BATCH; b += 256) {
        int m = b * SEQ + n;
        float s = g_scorep[m] + g_scorep[M2 + m];
        mx = fmaxf(mx, s);
    }
    red[tid] = mx;
    __syncthreads();
    for (int off = 128; off > 0; off >>= 1) {
        if (tid < off) red[tid] = fmaxf(red[tid], red[tid + off]);
        __syncthreads();
    }
    mx = red[0];
    __syncthreads();

    float sum = 0.f;
    for (int b = tid; b < BATCH; b += 256) {
        int m = b * SEQ + n;
        float s = g_scorep[m] + g_scorep[M2 + m];
        sum += expf(s - mx);
    }
    red[tid] = sum;
    __syncthreads();
    for (int off = 128; off > 0; off >>= 1) {
        if (tid < off) red[tid] += red[tid + off];
        __syncthreads();
    }
    float inv = 1.f / red[0];

    for (int b = tid; b < BATCH; b += 256) {
        int m = b * SEQ + n;
        float s  = g_scorep[m] + g_scorep[M2 + m];
        float al = expf(s - mx) * inv;
        if (title[m] == 0) al = 0.f;
        g_alpha[m] = al;
    }
}

// ---------------------------------------------------------------------------
// Kernel 5: pooling  out[b][f] = sum_n alpha[b,n] * C[b,n,f]
// ---------------------------------------------------------------------------
__global__ void pool_kernel(float* __restrict__ out)
{
    int b   = blockIdx.x;
    int tid = threadIdx.x;
    __shared__ float al[SEQ];
    if (tid < SEQ) al[tid] = g_alpha[b * SEQ + tid];
    __syncthreads();
    if (tid >= FILT / 4) return;
    int off = tid * 4;
    const float* base = g_C + (size_t)b * SEQ * FILT + off;
    float4 acc = make_float4(0.f, 0.f, 0.f, 0.f);
#pragma unroll
    for (int n = 0; n < SEQ; n++) {
        float a = al[n];
        float4 c = *(const float4*)(base + (size_t)n * FILT);
        acc.x = fmaf(a, c.x, acc.x); acc.y = fmaf(a, c.y, acc.y);
        acc.z = fmaf(a, c.z, acc.z); acc.w = fmaf(a, c.w, acc.w);
    }
    *(float4*)(out + (size_t)b * FILT + off) = acc;
}

// ---------------------------------------------------------------------------
// Launch
// ---------------------------------------------------------------------------
extern "C" void kernel_launch(void* const* d_in, const int* in_sizes, int n_in,
                              void* d_out, int out_size)
{
    const int*   title  = (const int*)  d_in[0];
    const float* emb    = (const float*)d_in[1];
    const float* conv_w = (const float*)d_in[2];
    const float* conv_b = (const float*)d_in[3];
    const float* v      = (const float*)d_in[4];
    const float* vb     = (const float*)d_in[5];
    const float* q      = (const float*)d_in[6];
    float*       out    = (float*)d_out;

    cudaFuncSetAttribute(gemm_P_mma,  cudaFuncAttributeMaxDynamicSharedMemorySize, DYN_SMEM);
    cudaFuncSetAttribute(gemm_att_mma, cudaFuncAttributeMaxDynamicSharedMemorySize, DYN_SMEM);

    prep_kernel<<<2048, 256>>>(emb, conv_w, v, vb, q);

    dim3 g1(GN / 128, MPAD / 128);                   // (10, 391)
    gemm_P_mma<<<g1, 256, DYN_SMEM>>>();

    assemble_kernel<<<M2, 128>>>(title, conv_b);

    dim3 g3(NPAD / 128, M2 / 128);                   // (2, 960)
    gemm_att_mma<<<g3, 256, DYN_SMEM>>>();

    softmax_kernel<<<SEQ, 256>>>(title);

    pool_kernel<<<BATCH, 128>>>(out);
}

// round 12
// speedup vs baseline: 2.1595x; 1.0847x over previous
#include <cuda_runtime.h>
#include <cuda_bf16.h>
#include <cstdint>

// Problem constants
#define VOCAB 50000
#define MPAD  50048              // 391 * 128
#define EMB   300
#define FILT  400
#define ATT   200
#define KW    3
#define BATCH 4096
#define SEQ   30
#define M2    (BATCH * SEQ)      // 122880
#define GN    1280               // 3*400 padded to 1280
#define NPAD  256                // ATT padded 200 -> 256

// GEMM1: virtual K = 960 (3 terms x 320); A stored as [hi|lo] = 640 cols,
//        third (hi) term redirected to cols 0..319 at load time.
#define KV1   960
#define KSA1  640
#define KB1   960
#define NC1   15                 // 960/64
// GEMM2: virtual K = 1216 (hi|lo|hi|pad16); A stored as [hi|lo|zero32] = 832,
//        cols 800..1199 redirect to 0..399, cols 1200..1215 redirect to the
//        never-written (zero) 800..831 region.
#define KV2   1216
#define KSA2  832
#define KB2   1216
#define NC2   19                 // 1216/64

// ---------------------------------------------------------------------------
// Scratch (static device globals; zero-initialized at module load)
// ---------------------------------------------------------------------------
__device__ __nv_bfloat16 g_Abf[(size_t)MPAD * KSA1]; // emb split [hi|lo]
__device__ __nv_bfloat16 g_Bbf[(size_t)GN * KB1];    // G split  [hi;hi;lo], [N][K]
__device__ float         g_P[(size_t)VOCAB * GN];    // vocab projection fp32
__device__ __nv_bfloat16 g_Cbf[(size_t)M2 * KSA2];   // relu(conv) split [hi|lo|0]
__device__ __nv_bfloat16 g_VPbf[(size_t)NPAD * KB2]; // v split [hi|hi|lo|0], [N][K]
__device__ float         g_vbp[NPAD];
__device__ float         g_qp[NPAD];
__device__ float         g_scorep[2 * M2];
__device__ float         g_alpha[M2];

// ---------------------------------------------------------------------------
// Kernel 0: build bf16-split operands + padded attention weights.
// ---------------------------------------------------------------------------
__global__ void prep_kernel(const float* __restrict__ emb,
                            const float* __restrict__ conv_w,
                            const float* __restrict__ v,
                            const float* __restrict__ vb,
                            const float* __restrict__ q)
{
    size_t i      = (size_t)blockIdx.x * blockDim.x + threadIdx.x;
    size_t stride = (size_t)gridDim.x * blockDim.x;

    // A' = emb split: [hi (0..319) | lo (320..639)]; pad k 300..319 zero
    for (size_t idx = i; idx < (size_t)VOCAB * KSA1; idx += stride) {
        int m  = (int)(idx / KSA1);
        int kp = (int)(idx % KSA1);
        int t  = kp / 320, k = kp - t * 320;
        float out = 0.f;
        if (k < EMB) {
            float x  = emb[(size_t)m * EMB + k];
            float hi = __bfloat162float(__float2bfloat16(x));
            out = t ? (x - hi) : hi;
        }
        g_Abf[idx] = __float2bfloat16(out);
    }

    // B' = G split, N-major: n = kk*400+f, G[k][n] = conv_w[f][k][kk]; {hi,hi,lo}
    for (size_t idx = i; idx < (size_t)GN * KB1; idx += stride) {
        int n  = (int)(idx / KB1);
        int kp = (int)(idx % KB1);
        int t  = kp / 320, k = kp - t * 320;
        float out = 0.f;
        if (k < EMB && n < KW * FILT) {
            int kk = n / FILT, f = n - kk * FILT;
            float x  = conv_w[(size_t)f * (EMB * KW) + k * KW + kk];
            float hi = __bfloat162float(__float2bfloat16(x));
            out = (t == 2) ? (x - hi) : hi;
        }
        g_Bbf[idx] = __float2bfloat16(out);
    }

    // VP' = v split, N-major: VP'[a][t*400+f] from v[f][a]; {hi,hi,lo};
    // rows a>=200 and cols>=1200 stay zero.
    for (size_t idx = i; idx < (size_t)NPAD * KB2; idx += stride) {
        int a  = (int)(idx / KB2);
        int kp = (int)(idx % KB2);
        float out = 0.f;
        if (kp < 1200 && a < ATT) {
            int t = kp / 400, f = kp - t * 400;
            float x  = v[(size_t)f * ATT + a];
            float hi = __bfloat162float(__float2bfloat16(x));
            out = (t == 2) ? (x - hi) : hi;
        }
        g_VPbf[idx] = __float2bfloat16(out);
    }

    if (i < NPAD) {
        g_vbp[i] = (i < ATT) ? vb[i] : 0.f;
        g_qp[i]  = (i < ATT) ? q[i]  : 0.f;
    }
}

// ---------------------------------------------------------------------------
// HMMA helpers (sm_80-era instructions: compile on family target)
// ---------------------------------------------------------------------------
__device__ __forceinline__ uint32_t smem_u32(const void* p) {
    uint32_t r;
    asm("{ .reg .u64 t; cvta.to.shared.u64 t, %1; cvt.u32.u64 %0, t; }"
        : "=r"(r) : "l"(p));
    return r;
}
#define SWZ(x) ((x) ^ (((x) >> 3) & 0x70))

__device__ __forceinline__ void ldm4(uint32_t* r, uint32_t addr) {
    asm volatile("ldmatrix.sync.aligned.m8n8.x4.shared.b16 {%0,%1,%2,%3}, [%4];"
                 : "=r"(r[0]), "=r"(r[1]), "=r"(r[2]), "=r"(r[3]) : "r"(addr));
}
__device__ __forceinline__ void mma16816(float* c, const uint32_t* a,
                                         uint32_t b0, uint32_t b1) {
    asm volatile(
        "mma.sync.aligned.m16n8k16.row.col.f32.bf16.bf16.f32 "
        "{%0,%1,%2,%3}, {%4,%5,%6,%7}, {%8,%9}, {%0,%1,%2,%3};"
        : "+f"(c[0]), "+f"(c[1]), "+f"(c[2]), "+f"(c[3])
        : "r"(a[0]), "r"(a[1]), "r"(a[2]), "r"(a[3]), "r"(b0), "r"(b1));
}
__device__ __forceinline__ void cpasync16(uint32_t s, const void* g) {
    asm volatile(
        "{ .reg .u64 ga; cvta.to.global.u64 ga, %1; "
        "cp.async.cg.shared.global [%0], [ga], 16; }"
        :: "r"(s), "l"(g) : "memory");
}
#define CP_COMMIT() asm volatile("cp.async.commit_group;" ::: "memory")
#define CP_WAIT1()  asm volatile("cp.async.wait_group 1;" ::: "memory")
#define CP_WAIT0()  asm volatile("cp.async.wait_group 0;" ::: "memory")

#define STG_BYTES 32768          // 16KB A + 16KB B per stage
#define DYN_SMEM  (3 * STG_BYTES)

// Loop-invariant ldmatrix address components for the 128x128 tile,
// warp layout 2(m) x 4(n), warp tile 64x32.
struct LdmAddr {
    uint32_t aoff[4], axm[4];    // A rows: wm + mi*16 + (lane&15)
    uint32_t boff[2], bxm[2];    // B rows: wn + bj*16 + (lane&15)  (B half offset folded)
    uint32_t colk[4];            // ks*32 + (lane>>4)*16
};
__device__ __forceinline__ LdmAddr make_ldm(int wm, int wn, int lane) {
    LdmAddr L;
#pragma unroll
    for (int mi = 0; mi < 4; mi++) {
        int r = wm + mi * 16 + (lane & 15);
        L.aoff[mi] = (uint32_t)r * 128;
        L.axm[mi]  = ((uint32_t)r << 4) & 0x70;
    }
#pragma unroll
    for (int bj = 0; bj < 2; bj++) {
        int r = wn + bj * 16 + (lane & 15);
        L.boff[bj] = 16384u + (uint32_t)r * 128;
        L.bxm[bj]  = ((uint32_t)r << 4) & 0x70;
    }
#pragma unroll
    for (int ks = 0; ks < 4; ks++)
        L.colk[ks] = (uint32_t)ks * 32 + ((lane >> 4) << 4);
    return L;
}

// One chunk of MMA work on stage buffer at sbuf.
__device__ __forceinline__ void mma_chunk(uint32_t sbuf, const LdmAddr& L,
                                          float acc[4][4][4]) {
#pragma unroll
    for (int ks = 0; ks < 4; ks++) {
        uint32_t af[4][4], bf2[2][4];
#pragma unroll
        for (int mi = 0; mi < 4; mi++)
            ldm4(af[mi], sbuf + L.aoff[mi] + (L.colk[ks] ^ L.axm[mi]));
#pragma unroll
        for (int bj = 0; bj < 2; bj++)
            ldm4(bf2[bj], sbuf + L.boff[bj] + (L.colk[ks] ^ L.bxm[bj]));
#pragma unroll
        for (int mi = 0; mi < 4; mi++)
#pragma unroll
            for (int nb = 0; nb < 4; nb++)
                mma16816(acc[mi][nb], af[mi],
                         bf2[nb >> 1][nb & 1], bf2[nb >> 1][(nb & 1) + 2]);
    }
}

// ---------------------------------------------------------------------------
// GEMM 1 (HMMA): g_P[50048 x 1280] = A'[.,960]virt @ B'^T, fp32 accum.
// Block 128x128, BK=64, 3-stage cp.async pipeline.
// ---------------------------------------------------------------------------
__global__ __launch_bounds__(256, 2) void gemm_P_mma()
{
    extern __shared__ __align__(128) uint8_t dyn[];
    int tid = threadIdx.x, w = tid >> 5, lane = tid & 31;
    int bM = blockIdx.y * 128, bN = blockIdx.x * 128;
    int wm = (w & 1) * 64, wn = (w >> 1) * 32;
    uint32_t sbase = smem_u32(dyn);
    LdmAddr L = make_ldm(wm, wn, lane);

    float acc[4][4][4];
#pragma unroll
    for (int i = 0; i < 4; i++)
#pragma unroll
        for (int j = 0; j < 4; j++)
#pragma unroll
            for (int k = 0; k < 4; k++) acc[i][j][k] = 0.f;

    int ld_row = tid >> 3, ld_c16 = tid & 7;
    uint32_t so0 = SWZ((uint32_t)(ld_row * 128 + ld_c16 * 16));

    auto issue = [&](int c, int b) {
        uint32_t sA = sbase + (uint32_t)b * STG_BYTES, sB = sA + 16384;
        int k0 = c * 64;
#pragma unroll
        for (int i = 0; i < 4; i++) {
            int row = ld_row + i * 32;
            uint32_t so = so0 + (uint32_t)i * 32 * 128;
            int s  = k0 + ld_c16 * 8;
            int sa = (s >= KSA1) ? s - KSA1 : s;      // hi-term redirect
            cpasync16(sA + so, g_Abf + (size_t)(bM + row) * KSA1 + sa);
            cpasync16(sB + so, g_Bbf + (size_t)(bN + row) * KB1 + s);
        }
        CP_COMMIT();
    };

    issue(0, 0); issue(1, 1);
    for (int c = 0; c < NC1; c++) {
        if (c + 1 < NC1) { CP_WAIT1(); } else { CP_WAIT0(); }
        __syncthreads();
        if (c + 2 < NC1) issue(c + 2, (c + 2) % 3);
        mma_chunk(sbase + (uint32_t)(c % 3) * STG_BYTES, L, acc);
        __syncthreads();
    }

    int r0 = lane >> 2, cB = (lane & 3) * 2;
#pragma unroll
    for (int mi = 0; mi < 4; mi++) {
        int row = bM + wm + mi * 16 + r0;
#pragma unroll
        for (int nb = 0; nb < 4; nb++) {
            int col = bN + wn + nb * 8 + cB;
            if (row < VOCAB)
                *(float2*)(g_P + (size_t)row * GN + col)
                    = make_float2(acc[mi][nb][0], acc[mi][nb][1]);
            if (row + 8 < VOCAB)
                *(float2*)(g_P + (size_t)(row + 8) * GN + col)
                    = make_float2(acc[mi][nb][2], acc[mi][nb][3]);
        }
    }
}

// ---------------------------------------------------------------------------
// Kernel 2: assemble conv rows (3 gathered P rows + bias, relu) -> bf16 split
// rows [hi | lo] of g_Cbf.  fp32 C is NOT materialized (pool reads hi+lo).
// ---------------------------------------------------------------------------
__global__ void assemble_kernel(const int* __restrict__ title,
                                const float* __restrict__ conv_b)
{
    int m   = blockIdx.x;
    int tid = threadIdx.x;
    if (tid >= FILT / 4) return;
    int n = m % SEQ;
    int off = tid * 4;

    float4 acc = *(const float4*)(conv_b + off);

    int tcur = title[m];
    float4 x = *(const float4*)(g_P + (size_t)tcur * GN + 1 * FILT + off);
    acc.x += x.x; acc.y += x.y; acc.z += x.z; acc.w += x.w;

    if (n > 0) {
        int tp = title[m - 1];
        float4 y = *(const float4*)(g_P + (size_t)tp * GN + 0 * FILT + off);
        acc.x += y.x; acc.y += y.y; acc.z += y.z; acc.w += y.w;
    }
    if (n < SEQ - 1) {
        int tn = title[m + 1];
        float4 z = *(const float4*)(g_P + (size_t)tn * GN + 2 * FILT + off);
        acc.x += z.x; acc.y += z.y; acc.z += z.z; acc.w += z.w;
    }
    acc.x = fmaxf(acc.x, 0.f); acc.y = fmaxf(acc.y, 0.f);
    acc.z = fmaxf(acc.z, 0.f); acc.w = fmaxf(acc.w, 0.f);

    float vv[4] = {acc.x, acc.y, acc.z, acc.w};
    unsigned short hu[4], lu[4];
#pragma unroll
    for (int i = 0; i < 4; i++) {
        __nv_bfloat16 h = __float2bfloat16(vv[i]);
        float lo = vv[i] - __bfloat162float(h);
        hu[i] = __bfloat16_as_ushort(h);
        lu[i] = __bfloat16_as_ushort(__float2bfloat16(lo));
    }
    uint2 hv = make_uint2((uint32_t)hu[0] | ((uint32_t)hu[1] << 16),
                          (uint32_t)hu[2] | ((uint32_t)hu[3] << 16));
    uint2 lv = make_uint2((uint32_t)lu[0] | ((uint32_t)lu[1] << 16),
                          (uint32_t)lu[2] | ((uint32_t)lu[3] << 16));
    __nv_bfloat16* cb = g_Cbf + (size_t)m * KSA2;
    *(uint2*)(cb + off)       = hv;
    *(uint2*)(cb + 400 + off) = lv;
    // cols 800..831 stay zero (zero-init, never written) — used as the
    // virtual-pad source in the attention GEMM redirect.
}

// ---------------------------------------------------------------------------
// GEMM 3 (HMMA) + fused attention epilogue:
//   S = Cbf[122880 x 1216]virt @ VPbf^T[256 x 1216]
//   scorep[col_block][m] = sum_a tanh(S[m,a]+vb[a]) * q[a]
// ---------------------------------------------------------------------------
__global__ __launch_bounds__(256, 2) void gemm_att_mma()
{
    extern __shared__ __align__(128) uint8_t dyn[];
    int tid = threadIdx.x, w = tid >> 5, lane = tid & 31;
    int bM = blockIdx.y * 128, bN = blockIdx.x * 128;
    int wm = (w & 1) * 64, wn = (w >> 1) * 32;
    uint32_t sbase = smem_u32(dyn);
    LdmAddr L = make_ldm(wm, wn, lane);

    float acc[4][4][4];
#pragma unroll
    for (int i = 0; i < 4; i++)
#pragma unroll
        for (int j = 0; j < 4; j++)
#pragma unroll
            for (int k = 0; k < 4; k++) acc[i][j][k] = 0.f;

    int ld_row = tid >> 3, ld_c16 = tid & 7;
    uint32_t so0 = SWZ((uint32_t)(ld_row * 128 + ld_c16 * 16));

    auto issue = [&](int c, int b) {
        uint32_t sA = sbase + (uint32_t)b * STG_BYTES, sB = sA + 16384;
        int k0 = c * 64;
#pragma unroll
        for (int i = 0; i < 4; i++) {
            int row = ld_row + i * 32;
            uint32_t so = so0 + (uint32_t)i * 32 * 128;
            int s  = k0 + ld_c16 * 8;
            // virtual->stored: [0,800)->s, [800,1200)->s-800, [1200,1216)->zeros
            int sa = (s < 800) ? s : ((s < 1200) ? s - 800 : s - 400);
            cpasync16(sA + so, g_Cbf  + (size_t)(bM + row) * KSA2 + sa);
            cpasync16(sB + so, g_VPbf + (size_t)(bN + row) * KB2 + s);
        }
        CP_COMMIT();
    };

    issue(0, 0); issue(1, 1);
    for (int c = 0; c < NC2; c++) {
        if (c + 1 < NC2) { CP_WAIT1(); } else { CP_WAIT0(); }
        __syncthreads();
        if (c + 2 < NC2) issue(c + 2, (c + 2) % 3);
        mma_chunk(sbase + (uint32_t)(c % 3) * STG_BYTES, L, acc);
        __syncthreads();
    }

    // Fused epilogue: per-row sum of tanh(S+vb)*q over this block's 128 cols.
    float rp[4][2];
#pragma unroll
    for (int mi = 0; mi < 4; mi++) { rp[mi][0] = 0.f; rp[mi][1] = 0.f; }
#pragma unroll
    for (int nb = 0; nb < 4; nb++) {
        int gc = bN + wn + nb * 8 + (lane & 3) * 2;
        float vb0 = g_vbp[gc], vb1 = g_vbp[gc + 1];
        float q0  = g_qp[gc],  q1  = g_qp[gc + 1];
#pragma unroll
        for (int mi = 0; mi < 4; mi++) {
            rp[mi][0] += tanhf(acc[mi][nb][0] + vb0) * q0
                       + tanhf(acc[mi][nb][1] + vb1) * q1;
            rp[mi][1] += tanhf(acc[mi][nb][2] + vb0) * q0
                       + tanhf(acc[mi][nb][3] + vb1) * q1;
        }
    }
#pragma unroll
    for (int mi = 0; mi < 4; mi++)
#pragma unroll
        for (int h = 0; h < 2; h++) {
            rp[mi][h] += __shfl_xor_sync(0xffffffffu, rp[mi][h], 1);
            rp[mi][h] += __shfl_xor_sync(0xffffffffu, rp[mi][h], 2);
        }

    float* red = (float*)dyn;     // reuse tile SMEM (all reads done)
    if ((lane & 3) == 0) {
#pragma unroll
        for (int mi = 0; mi < 4; mi++)
#pragma unroll
            for (int h = 0; h < 2; h++) {
                int row = wm + mi * 16 + (lane >> 2) + h * 8;
                red[row * 4 + (w >> 1)] = rp[mi][h];
            }
    }
    __syncthreads();
    if (tid < 128) {
        float s = red[tid * 4 + 0] + red[tid * 4 + 1]
                + red[tid * 4 + 2] + red[tid * 4 + 3];
        g_scorep[(size_t)blockIdx.x * M2 + bM + tid] = s;
    }
}

// ---------------------------------------------------------------------------
// Kernel 4: softmax over batch dim (per position n), masked.
// ---------------------------------------------------------------------------
__global__ void softmax_kernel(const int* __restrict__ title)
{
    int n   = blockIdx.x;
    int tid = threadIdx.x;
    __shared__ float red[256];

    float mx = -3.4e38f;
    for (int b = tid; b < BATCH; b += 256) {
        int m = b * SEQ + n;
        float s = g_scorep[m] + g_scorep[M2 + m];
        mx = fmaxf(mx, s);
    }
    red[tid] = mx;
    __syncthreads();
    for (int off = 128; off > 0; off >>= 1) {
        if (tid < off) red[tid] = fmaxf(red[tid], red[tid + off]);
        __syncthreads();
    }
    mx = red[0];
    __syncthreads();

    float sum = 0.f;
    for (int b = tid; b < BATCH; b += 256) {
        int m = b * SEQ + n;
        float s = g_scorep[m] + g_scorep[M2 + m];
        sum += expf(s - mx);
    }
    red[tid] = sum;
    __syncthreads();
    for (int off = 128; off > 0; off >>= 1) {
        if (tid < off) red[tid] += red[tid + off];
        __syncthreads();
    }
    float inv = 1.f / red[0];

    for (int b = tid; b < BATCH; b += 256) {
        int m = b * SEQ + n;
        float s  = g_scorep[m] + g_scorep[M2 + m];
        float al = expf(s - mx) * inv;
        if (title[m] == 0) al = 0.f;
        g_alpha[m] = al;
    }
}

// ---------------------------------------------------------------------------
// Kernel 5: pooling  out[b][f] = sum_n alpha[b,n] * (Cbf_hi + Cbf_lo)[b,n,f]
// ---------------------------------------------------------------------------
__global__ void pool_kernel(float* __restrict__ out)
{
    int b   = blockIdx.x;
    int tid = threadIdx.x;
    __shared__ float al[SEQ];
    if (tid < SEQ) al[tid] = g_alpha[b * SEQ + tid];
    __syncthreads();
    if (tid >= FILT / 4) return;
    int off = tid * 4;
    const __nv_bfloat16* base = g_Cbf + (size_t)b * SEQ * KSA2 + off;
    float4 acc = make_float4(0.f, 0.f, 0.f, 0.f);
#pragma unroll
    for (int n = 0; n < SEQ; n++) {
        float a = al[n];
        const __nv_bfloat16* row = base + (size_t)n * KSA2;
        __nv_bfloat162 h0 = *(const __nv_bfloat162*)(row);
        __nv_bfloat162 h1 = *(const __nv_bfloat162*)(row + 2);
        __nv_bfloat162 l0 = *(const __nv_bfloat162*)(row + 400);
        __nv_bfloat162 l1 = *(const __nv_bfloat162*)(row + 402);
        acc.x = fmaf(a, __bfloat162float(h0.x) + __bfloat162float(l0.x), acc.x);
        acc.y = fmaf(a, __bfloat162float(h0.y) + __bfloat162float(l0.y), acc.y);
        acc.z = fmaf(a, __bfloat162float(h1.x) + __bfloat162float(l1.x), acc.z);
        acc.w = fmaf(a, __bfloat162float(h1.y) + __bfloat162float(l1.y), acc.w);
    }
    *(float4*)(out + (size_t)b * FILT + off) = acc;
}

// ---------------------------------------------------------------------------
// Launch
// ---------------------------------------------------------------------------
extern "C" void kernel_launch(void* const* d_in, const int* in_sizes, int n_in,
                              void* d_out, int out_size)
{
    const int*   title  = (const int*)  d_in[0];
    const float* emb    = (const float*)d_in[1];
    const float* conv_w = (const float*)d_in[2];
    const float* conv_b = (const float*)d_in[3];
    const float* v      = (const float*)d_in[4];
    const float* vb     = (const float*)d_in[5];
    const float* q      = (const float*)d_in[6];
    float*       out    = (float*)d_out;

    cudaFuncSetAttribute(gemm_P_mma,   cudaFuncAttributeMaxDynamicSharedMemorySize, DYN_SMEM);
    cudaFuncSetAttribute(gemm_att_mma, cudaFuncAttributeMaxDynamicSharedMemorySize, DYN_SMEM);

    prep_kernel<<<2048, 256>>>(emb, conv_w, v, vb, q);

    dim3 g1(GN / 128, MPAD / 128);                   // (10, 391)
    gemm_P_mma<<<g1, 256, DYN_SMEM>>>();

    assemble_kernel<<<M2, 128>>>(title, conv_b);

    dim3 g3(NPAD / 128, M2 / 128);                   // (2, 960)
    gemm_att_mma<<<g3, 256, DYN_SMEM>>>();

    softmax_kernel<<<SEQ, 256>>>(title);

    pool_kernel<<<BATCH, 128>>>(out);
}

// round 13
// speedup vs baseline: 2.1869x; 1.0126x over previous
#include <cuda_runtime.h>
#include <cuda_bf16.h>
#include <cstdint>

// Problem constants
#define VOCAB 50000
#define MPAD  50048              // 391 * 128
#define EMB   300
#define FILT  400
#define ATT   200
#define KW    3
#define BATCH 4096
#define SEQ   30
#define M2    (BATCH * SEQ)      // 122880
#define GN    1280               // 3*400 padded to 1280
#define NPAD  256                // ATT padded 200 -> 256

// GEMM1: virtual K = 960 (3 terms x 320); A stored as [hi|lo] = 640 cols,
//        third (hi) term redirected to cols 0..319 at load time (uniform
//        wrap at chunk c==10 for all threads).
#define KV1   960
#define KSA1  640
#define KB1   960
#define NC1   15                 // 960/64
// GEMM2: virtual K = 1216 (hi|lo|hi|pad16); A stored as [hi|lo|zero32] = 832,
//        cols 800..1199 redirect to 0..399, cols 1200..1215 redirect to the
//        never-written (zero) 800..831 region.
#define KV2   1216
#define KSA2  832
#define KB2   1216
#define NC2   19                 // 1216/64

// ---------------------------------------------------------------------------
// Scratch (static device globals; zero-initialized at module load)
// ---------------------------------------------------------------------------
__device__ __nv_bfloat16 g_Abf[(size_t)MPAD * KSA1]; // emb split [hi|lo]
__device__ __nv_bfloat16 g_Bbf[(size_t)GN * KB1];    // G split  [hi;hi;lo], [N][K]
__device__ float         g_P[(size_t)VOCAB * GN];    // vocab projection fp32
__device__ __nv_bfloat16 g_Cbf[(size_t)M2 * KSA2];   // relu(conv) split [hi|lo|0]
__device__ __nv_bfloat16 g_VPbf[(size_t)NPAD * KB2]; // v split [hi|hi|lo|0], [N][K]
__device__ float         g_vbp[NPAD];
__device__ float         g_qp[NPAD];
__device__ float         g_scorep[2 * M2];
__device__ float         g_alpha[M2];

// ---------------------------------------------------------------------------
// Kernel 0: build bf16-split operands + padded attention weights.
// ---------------------------------------------------------------------------
__global__ void prep_kernel(const float* __restrict__ emb,
                            const float* __restrict__ conv_w,
                            const float* __restrict__ v,
                            const float* __restrict__ vb,
                            const float* __restrict__ q)
{
    size_t i      = (size_t)blockIdx.x * blockDim.x + threadIdx.x;
    size_t stride = (size_t)gridDim.x * blockDim.x;

    // A' = emb split: [hi (0..319) | lo (320..639)]; pad k 300..319 zero
    for (size_t idx = i; idx < (size_t)VOCAB * KSA1; idx += stride) {
        int m  = (int)(idx / KSA1);
        int kp = (int)(idx % KSA1);
        int t  = kp / 320, k = kp - t * 320;
        float out = 0.f;
        if (k < EMB) {
            float x  = emb[(size_t)m * EMB + k];
            float hi = __bfloat162float(__float2bfloat16(x));
            out = t ? (x - hi) : hi;
        }
        g_Abf[idx] = __float2bfloat16(out);
    }

    // B' = G split, N-major: n = kk*400+f, G[k][n] = conv_w[f][k][kk]; {hi,hi,lo}
    for (size_t idx = i; idx < (size_t)GN * KB1; idx += stride) {
        int n  = (int)(idx / KB1);
        int kp = (int)(idx % KB1);
        int t  = kp / 320, k = kp - t * 320;
        float out = 0.f;
        if (k < EMB && n < KW * FILT) {
            int kk = n / FILT, f = n - kk * FILT;
            float x  = conv_w[(size_t)f * (EMB * KW) + k * KW + kk];
            float hi = __bfloat162float(__float2bfloat16(x));
            out = (t == 2) ? (x - hi) : hi;
        }
        g_Bbf[idx] = __float2bfloat16(out);
    }

    // VP' = v split, N-major: VP'[a][t*400+f] from v[f][a]; {hi,hi,lo};
    // rows a>=200 and cols>=1200 stay zero.
    for (size_t idx = i; idx < (size_t)NPAD * KB2; idx += stride) {
        int a  = (int)(idx / KB2);
        int kp = (int)(idx % KB2);
        float out = 0.f;
        if (kp < 1200 && a < ATT) {
            int t = kp / 400, f = kp - t * 400;
            float x  = v[(size_t)f * ATT + a];
            float hi = __bfloat162float(__float2bfloat16(x));
            out = (t == 2) ? (x - hi) : hi;
        }
        g_VPbf[idx] = __float2bfloat16(out);
    }

    if (i < NPAD) {
        g_vbp[i] = (i < ATT) ? vb[i] : 0.f;
        g_qp[i]  = (i < ATT) ? q[i]  : 0.f;
    }
}

// ---------------------------------------------------------------------------
// HMMA helpers (sm_80-era instructions: compile on family target)
// ---------------------------------------------------------------------------
__device__ __forceinline__ uint32_t smem_u32(const void* p) {
    uint32_t r;
    asm("{ .reg .u64 t; cvta.to.shared.u64 t, %1; cvt.u32.u64 %0, t; }"
        : "=r"(r) : "l"(p));
    return r;
}
#define SWZ(x) ((x) ^ (((x) >> 3) & 0x70))

__device__ __forceinline__ void ldm4(uint32_t* r, uint32_t addr) {
    asm volatile("ldmatrix.sync.aligned.m8n8.x4.shared.b16 {%0,%1,%2,%3}, [%4];"
                 : "=r"(r[0]), "=r"(r[1]), "=r"(r[2]), "=r"(r[3]) : "r"(addr));
}
__device__ __forceinline__ void mma16816(float* c, const uint32_t* a,
                                         uint32_t b0, uint32_t b1) {
    asm volatile(
        "mma.sync.aligned.m16n8k16.row.col.f32.bf16.bf16.f32 "
        "{%0,%1,%2,%3}, {%4,%5,%6,%7}, {%8,%9}, {%0,%1,%2,%3};"
        : "+f"(c[0]), "+f"(c[1]), "+f"(c[2]), "+f"(c[3])
        : "r"(a[0]), "r"(a[1]), "r"(a[2]), "r"(a[3]), "r"(b0), "r"(b1));
}
__device__ __forceinline__ void cpasync16(uint32_t s, const void* g) {
    asm volatile(
        "{ .reg .u64 ga; cvta.to.global.u64 ga, %1; "
        "cp.async.cg.shared.global [%0], [ga], 16; }"
        :: "r"(s), "l"(g) : "memory");
}
#define CP_COMMIT() asm volatile("cp.async.commit_group;" ::: "memory")
#define CP_WAIT1()  asm volatile("cp.async.wait_group 1;" ::: "memory")
#define CP_WAIT0()  asm volatile("cp.async.wait_group 0;" ::: "memory")

#define STG_BYTES 32768          // 16KB A + 16KB B per stage
#define DYN_SMEM  (3 * STG_BYTES)

// Loop-invariant ldmatrix address components for the 128x128 tile,
// warp layout 2(m) x 4(n), warp tile 64x32.
struct LdmAddr {
    uint32_t aoff[4], axm[4];    // A rows: wm + mi*16 + (lane&15)
    uint32_t boff[2], bxm[2];    // B rows (B half offset folded)
    uint32_t colk[4];            // ks*32 + (lane>>4)*16
};
__device__ __forceinline__ LdmAddr make_ldm(int wm, int wn, int lane) {
    LdmAddr L;
#pragma unroll
    for (int mi = 0; mi < 4; mi++) {
        int r = wm + mi * 16 + (lane & 15);
        L.aoff[mi] = (uint32_t)r * 128;
        L.axm[mi]  = ((uint32_t)r << 4) & 0x70;
    }
#pragma unroll
    for (int bj = 0; bj < 2; bj++) {
        int r = wn + bj * 16 + (lane & 15);
        L.boff[bj] = 16384u + (uint32_t)r * 128;
        L.bxm[bj]  = ((uint32_t)r << 4) & 0x70;
    }
#pragma unroll
    for (int ks = 0; ks < 4; ks++)
        L.colk[ks] = (uint32_t)ks * 32 + ((lane >> 4) << 4);
    return L;
}

// One chunk of MMA work on stage buffer at sbuf.
__device__ __forceinline__ void mma_chunk(uint32_t sbuf, const LdmAddr& L,
                                          float acc[4][4][4]) {
#pragma unroll
    for (int ks = 0; ks < 4; ks++) {
        uint32_t af[4][4], bf2[2][4];
#pragma unroll
        for (int mi = 0; mi < 4; mi++)
            ldm4(af[mi], sbuf + L.aoff[mi] + (L.colk[ks] ^ L.axm[mi]));
#pragma unroll
        for (int bj = 0; bj < 2; bj++)
            ldm4(bf2[bj], sbuf + L.boff[bj] + (L.colk[ks] ^ L.bxm[bj]));
#pragma unroll
        for (int mi = 0; mi < 4; mi++)
#pragma unroll
            for (int nb = 0; nb < 4; nb++)
                mma16816(acc[mi][nb], af[mi],
                         bf2[nb >> 1][nb & 1], bf2[nb >> 1][(nb & 1) + 2]);
    }
}

// ---------------------------------------------------------------------------
// GEMM 1 (HMMA): g_P[50048 x 1280] = A'[.,960]virt @ B'^T, fp32 accum.
// Block 128x128, BK=64, 3-stage cp.async pipeline, single sync per iter.
// ---------------------------------------------------------------------------
__global__ __launch_bounds__(256, 2) void gemm_P_mma()
{
    extern __shared__ __align__(128) uint8_t dyn[];
    int tid = threadIdx.x, w = tid >> 5, lane = tid & 31;
    int bM = blockIdx.y * 128, bN = blockIdx.x * 128;
    int wm = (w & 1) * 64, wn = (w >> 1) * 32;
    uint32_t sbase = smem_u32(dyn);
    LdmAddr L = make_ldm(wm, wn, lane);

    float acc[4][4][4];
#pragma unroll
    for (int i = 0; i < 4; i++)
#pragma unroll
        for (int j = 0; j < 4; j++)
#pragma unroll
            for (int k = 0; k < 4; k++) acc[i][j][k] = 0.f;

    // Hoisted per-thread load bases (chunk-invariant).
    int ld_row = tid >> 3, ld_c16_8 = (tid & 7) * 8;
    uint32_t so0 = SWZ((uint32_t)(ld_row * 128 + ld_c16_8 * 2));
    const __nv_bfloat16* baA[4];
    const __nv_bfloat16* baB[4];
    uint32_t soi[4];
#pragma unroll
    for (int i = 0; i < 4; i++) {
        int row = ld_row + i * 32;
        baA[i] = g_Abf + (size_t)(bM + row) * KSA1;
        baB[i] = g_Bbf + (size_t)(bN + row) * KB1;
        soi[i] = so0 + (uint32_t)i * 32 * 128;
    }

    auto issue = [&](int c, int b) {
        uint32_t sA = sbase + (uint32_t)b * STG_BYTES;
        int v  = c * 64 + ld_c16_8;
        int sa = (c >= 10) ? v - KSA1 : v;   // uniform third-term wrap
#pragma unroll
        for (int i = 0; i < 4; i++) {
            cpasync16(sA + soi[i],          baA[i] + sa);
            cpasync16(sA + 16384 + soi[i],  baB[i] + v);
        }
        CP_COMMIT();
    };

    issue(0, 0); issue(1, 1);
    for (int c = 0; c < NC1; c++) {
        if (c + 1 < NC1) { CP_WAIT1(); } else { CP_WAIT0(); }
        __syncthreads();                      // stage c ready AND compute(c-1) done
        if (c + 2 < NC1) issue(c + 2, (c + 2) % 3);
        mma_chunk(sbase + (uint32_t)(c % 3) * STG_BYTES, L, acc);
    }

    int r0 = lane >> 2, cB = (lane & 3) * 2;
#pragma unroll
    for (int mi = 0; mi < 4; mi++) {
        int row = bM + wm + mi * 16 + r0;
#pragma unroll
        for (int nb = 0; nb < 4; nb++) {
            int col = bN + wn + nb * 8 + cB;
            if (row < VOCAB)
                *(float2*)(g_P + (size_t)row * GN + col)
                    = make_float2(acc[mi][nb][0], acc[mi][nb][1]);
            if (row + 8 < VOCAB)
                *(float2*)(g_P + (size_t)(row + 8) * GN + col)
                    = make_float2(acc[mi][nb][2], acc[mi][nb][3]);
        }
    }
}

// ---------------------------------------------------------------------------
// Kernel 2: assemble conv rows (3 gathered P rows + bias, relu) -> bf16 split
// rows [hi | lo] of g_Cbf.  fp32 C is NOT materialized (pool reads hi+lo).
// ---------------------------------------------------------------------------
__global__ void assemble_kernel(const int* __restrict__ title,
                                const float* __restrict__ conv_b)
{
    int m   = blockIdx.x;
    int tid = threadIdx.x;
    if (tid >= FILT / 4) return;
    int n = m % SEQ;
    int off = tid * 4;

    float4 acc = *(const float4*)(conv_b + off);

    int tcur = title[m];
    float4 x = *(const float4*)(g_P + (size_t)tcur * GN + 1 * FILT + off);
    acc.x += x.x; acc.y += x.y; acc.z += x.z; acc.w += x.w;

    if (n > 0) {
        int tp = title[m - 1];
        float4 y = *(const float4*)(g_P + (size_t)tp * GN + 0 * FILT + off);
        acc.x += y.x; acc.y += y.y; acc.z += y.z; acc.w += y.w;
    }
    if (n < SEQ - 1) {
        int tn = title[m + 1];
        float4 z = *(const float4*)(g_P + (size_t)tn * GN + 2 * FILT + off);
        acc.x += z.x; acc.y += z.y; acc.z += z.z; acc.w += z.w;
    }
    acc.x = fmaxf(acc.x, 0.f); acc.y = fmaxf(acc.y, 0.f);
    acc.z = fmaxf(acc.z, 0.f); acc.w = fmaxf(acc.w, 0.f);

    float vv[4] = {acc.x, acc.y, acc.z, acc.w};
    unsigned short hu[4], lu[4];
#pragma unroll
    for (int i = 0; i < 4; i++) {
        __nv_bfloat16 h = __float2bfloat16(vv[i]);
        float lo = vv[i] - __bfloat162float(h);
        hu[i] = __bfloat16_as_ushort(h);
        lu[i] = __bfloat16_as_ushort(__float2bfloat16(lo));
    }
    uint2 hv = make_uint2((uint32_t)hu[0] | ((uint32_t)hu[1] << 16),
                          (uint32_t)hu[2] | ((uint32_t)hu[3] << 16));
    uint2 lv = make_uint2((uint32_t)lu[0] | ((uint32_t)lu[1] << 16),
                          (uint32_t)lu[2] | ((uint32_t)lu[3] << 16));
    __nv_bfloat16* cb = g_Cbf + (size_t)m * KSA2;
    *(uint2*)(cb + off)       = hv;
    *(uint2*)(cb + 400 + off) = lv;
    // cols 800..831 stay zero (zero-init, never written) — used as the
    // virtual-pad source in the attention GEMM redirect.
}

// ---------------------------------------------------------------------------
// GEMM 3 (HMMA) + fused attention epilogue:
//   S = Cbf[122880 x 1216]virt @ VPbf^T[256 x 1216]
//   scorep[col_block][m] = sum_a tanh(S[m,a]+vb[a]) * q[a]
// ---------------------------------------------------------------------------
__global__ __launch_bounds__(256, 2) void gemm_att_mma()
{
    extern __shared__ __align__(128) uint8_t dyn[];
    int tid = threadIdx.x, w = tid >> 5, lane = tid & 31;
    int bM = blockIdx.y * 128, bN = blockIdx.x * 128;
    int wm = (w & 1) * 64, wn = (w >> 1) * 32;
    uint32_t sbase = smem_u32(dyn);
    LdmAddr L = make_ldm(wm, wn, lane);

    float acc[4][4][4];
#pragma unroll
    for (int i = 0; i < 4; i++)
#pragma unroll
        for (int j = 0; j < 4; j++)
#pragma unroll
            for (int k = 0; k < 4; k++) acc[i][j][k] = 0.f;

    int ld_row = tid >> 3, ld_c16_8 = (tid & 7) * 8;
    uint32_t so0 = SWZ((uint32_t)(ld_row * 128 + ld_c16_8 * 2));
    const __nv_bfloat16* baA[4];
    const __nv_bfloat16* baB[4];
    uint32_t soi[4];
#pragma unroll
    for (int i = 0; i < 4; i++) {
        int row = ld_row + i * 32;
        baA[i] = g_Cbf  + (size_t)(bM + row) * KSA2;
        baB[i] = g_VPbf + (size_t)(bN + row) * KB2;
        soi[i] = so0 + (uint32_t)i * 32 * 128;
    }

    auto issue = [&](int c, int b) {
        uint32_t sA = sbase + (uint32_t)b * STG_BYTES;
        int v  = c * 64 + ld_c16_8;
        // virtual->stored: [0,800)->v, [800,1200)->v-800, [1200,1216)->zeros
        int sa = (v < 800) ? v : ((v < 1200) ? v - 800 : v - 400);
#pragma unroll
        for (int i = 0; i < 4; i++) {
            cpasync16(sA + soi[i],         baA[i] + sa);
            cpasync16(sA + 16384 + soi[i], baB[i] + v);
        }
        CP_COMMIT();
    };

    issue(0, 0); issue(1, 1);
    for (int c = 0; c < NC2; c++) {
        if (c + 1 < NC2) { CP_WAIT1(); } else { CP_WAIT0(); }
        __syncthreads();
        if (c + 2 < NC2) issue(c + 2, (c + 2) % 3);
        mma_chunk(sbase + (uint32_t)(c % 3) * STG_BYTES, L, acc);
    }

    // Fused epilogue: per-row sum of tanh(S+vb)*q over this block's 128 cols.
    float rp[4][2];
#pragma unroll
    for (int mi = 0; mi < 4; mi++) { rp[mi][0] = 0.f; rp[mi][1] = 0.f; }
#pragma unroll
    for (int nb = 0; nb < 4; nb++) {
        int gc = bN + wn + nb * 8 + (lane & 3) * 2;
        float vb0 = g_vbp[gc], vb1 = g_vbp[gc + 1];
        float q0  = g_qp[gc],  q1  = g_qp[gc + 1];
#pragma unroll
        for (int mi = 0; mi < 4; mi++) {
            rp[mi][0] += tanhf(acc[mi][nb][0] + vb0) * q0
                       + tanhf(acc[mi][nb][1] + vb1) * q1;
            rp[mi][1] += tanhf(acc[mi][nb][2] + vb0) * q0
                       + tanhf(acc[mi][nb][3] + vb1) * q1;
        }
    }
#pragma unroll
    for (int mi = 0; mi < 4; mi++)
#pragma unroll
        for (int h = 0; h < 2; h++) {
            rp[mi][h] += __shfl_xor_sync(0xffffffffu, rp[mi][h], 1);
            rp[mi][h] += __shfl_xor_sync(0xffffffffu, rp[mi][h], 2);
        }

    __syncthreads();              // tile SMEM reads (last mma_chunk) complete
    float* red = (float*)dyn;     // reuse tile SMEM for the reduction
    if ((lane & 3) == 0) {
#pragma unroll
        for (int mi = 0; mi < 4; mi++)
#pragma unroll
            for (int h = 0; h < 2; h++) {
                int row = wm + mi * 16 + (lane >> 2) + h * 8;
                red[row * 4 + (w >> 1)] = rp[mi][h];
            }
    }
    __syncthreads();
    if (tid < 128) {
        float s = red[tid * 4 + 0] + red[tid * 4 + 1]
                + red[tid * 4 + 2] + red[tid * 4 + 3];
        g_scorep[(size_t)blockIdx.x * M2 + bM + tid] = s;
    }
}

// ---------------------------------------------------------------------------
// Kernel 4: softmax over batch dim (per position n), masked.
// ---------------------------------------------------------------------------
__global__ void softmax_kernel(const int* __restrict__ title)
{
    int n   = blockIdx.x;
    int tid = threadIdx.x;
    __shared__ float red[256];

    float mx = -3.4e38f;
    for (int b = tid; b < BATCH; b += 256) {
        int m = b * SEQ + n;
        float s = g_scorep[m] + g_scorep[M2 + m];
        mx = fmaxf(mx, s);
    }
    red[tid] = mx;
    __syncthreads();
    for (int off = 128; off > 0; off >>= 1) {
        if (tid < off) red[tid] = fmaxf(red[tid], red[tid + off]);
        __syncthreads();
    }
    mx = red[0];
    __syncthreads();

    float sum = 0.f;
    for (int b = tid; b < BATCH; b += 256) {
        int m = b * SEQ + n;
        float s = g_scorep[m] + g_scorep[M2 + m];
        sum += expf(s - mx);
    }
    red[tid] = sum;
    __syncthreads();
    for (int off = 128; off > 0; off >>= 1) {
        if (tid < off) red[tid] += red[tid + off];
        __syncthreads();
    }
    float inv = 1.f / red[0];

    for (int b = tid; b < BATCH; b += 256) {
        int m = b * SEQ + n;
        float s  = g_scorep[m] + g_scorep[M2 + m];
        float al = expf(s - mx) * inv;
        if (title[m] == 0) al = 0.f;
        g_alpha[m] = al;
    }
}

// ---------------------------------------------------------------------------
// Kernel 5: pooling  out[b][f] = sum_n alpha[b,n] * (Cbf_hi + Cbf_lo)[b,n,f]
// ---------------------------------------------------------------------------
__global__ void pool_kernel(float* __restrict__ out)
{
    int b   = blockIdx.x;
    int tid = threadIdx.x;
    __shared__ float al[SEQ];
    if (tid < SEQ) al[tid] = g_alpha[b * SEQ + tid];
    __syncthreads();
    if (tid >= FILT / 4) return;
    int off = tid * 4;
    const __nv_bfloat16* base = g_Cbf + (size_t)b * SEQ * KSA2 + off;
    float4 acc = make_float4(0.f, 0.f, 0.f, 0.f);
#pragma unroll
    for (int n = 0; n < SEQ; n++) {
        float a = al[n];
        const __nv_bfloat16* row = base + (size_t)n * KSA2;
        __nv_bfloat162 h0 = *(const __nv_bfloat162*)(row);
        __nv_bfloat162 h1 = *(const __nv_bfloat162*)(row + 2);
        __nv_bfloat162 l0 = *(const __nv_bfloat162*)(row + 400);
        __nv_bfloat162 l1 = *(const __nv_bfloat162*)(row + 402);
        acc.x = fmaf(a, __bfloat162float(h0.x) + __bfloat162float(l0.x), acc.x);
        acc.y = fmaf(a, __bfloat162float(h0.y) + __bfloat162float(l0.y), acc.y);
        acc.z = fmaf(a, __bfloat162float(h1.x) + __bfloat162float(l1.x), acc.z);
        acc.w = fmaf(a, __bfloat162float(h1.y) + __bfloat162float(l1.y), acc.w);
    }
    *(float4*)(out + (size_t)b * FILT + off) = acc;
}

// ---------------------------------------------------------------------------
// Launch
// ---------------------------------------------------------------------------
extern "C" void kernel_launch(void* const* d_in, const int* in_sizes, int n_in,
                              void* d_out, int out_size)
{
    const int*   title  = (const int*)  d_in[0];
    const float* emb    = (const float*)d_in[1];
    const float* conv_w = (const float*)d_in[2];
    const float* conv_b = (const float*)d_in[3];
    const float* v      = (const float*)d_in[4];
    const float* vb     = (const float*)d_in[5];
    const float* q      = (const float*)d_in[6];
    float*       out    = (float*)d_out;

    cudaFuncSetAttribute(gemm_P_mma,   cudaFuncAttributeMaxDynamicSharedMemorySize, DYN_SMEM);
    cudaFuncSetAttribute(gemm_att_mma, cudaFuncAttributeMaxDynamicSharedMemorySize, DYN_SMEM);

    prep_kernel<<<2048, 256>>>(emb, conv_w, v, vb, q);

    dim3 g1(GN / 128, MPAD / 128);                   // (10, 391)
    gemm_P_mma<<<g1, 256, DYN_SMEM>>>();

    assemble_kernel<<<M2, 128>>>(title, conv_b);

    dim3 g3(NPAD / 128, M2 / 128);                   // (2, 960)
    gemm_att_mma<<<g3, 256, DYN_SMEM>>>();

    softmax_kernel<<<SEQ, 256>>>(title);

    pool_kernel<<<BATCH, 128>>>(out);
}